// round 8
// baseline (speedup 1.0000x reference)
#include <cuda_runtime.h>
#include <cstdint>

#define HH 1024
#define WW 1024
#define HWs (HH*WW)
#define BIGV 1e9f
#define NEGB (-1e9f)
#define L2E 1.4426950408889634f

#define XW 71          // x window: [X0-3, X0+67]
#define PSTR 12        // floats per pixel slot (8 ch + 4 pad -> 48B, 16B aligned for LDS.128)
#define RSTR (XW*PSTR) // floats per row

typedef unsigned long long ull;

__device__ __forceinline__ ull pk(float a, float b) {
    ull r;
    asm("mov.b64 %0, {%1, %2};" : "=l"(r) : "f"(a), "f"(b));
    return r;
}
__device__ __forceinline__ void upk(ull v, float& a, float& b) {
    asm("mov.b64 {%0, %1}, %2;" : "=f"(a), "=f"(b) : "l"(v));
}
__device__ __forceinline__ ull fma2(ull a, ull b, ull c) {
    ull d;
    asm("fma.rn.f32x2 %0, %1, %2, %3;" : "=l"(d) : "l"(a), "l"(b), "l"(c));
    return d;
}
__device__ __forceinline__ ull add2(ull a, ull b) {
    ull d;
    asm("add.rn.f32x2 %0, %1, %2;" : "=l"(d) : "l"(a), "l"(b));
    return d;
}
__device__ __forceinline__ float ex2(float x) {
    float y;
    asm("ex2.approx.f32 %0, %1;" : "=f"(y) : "f"(x));
    return y;
}
__device__ __forceinline__ float frcp(float x) {
    float y;
    asm("rcp.approx.f32 %0, %1;" : "=f"(y) : "f"(x));
    return y;
}

// Tile 64 wide x 8 tall. Block (64,4); thread (tx,ty) owns pixels
// (X0+tx, Y0+2ty) and (X0+tx, Y0+2ty+1) — vertically adjacent; each loaded
// neighbor value serves BOTH pixels. SMEM channel-interleaved, 48B pixel slot,
// channels fetched by TWO LDS.128 (conflict-free at stride-12 words).
// R8: per-pixel logw chain split into two 4-deep fma2 chains (+1 add2) to
// halve the dependency depth; row loop unrolled x2 for cross-row MLP.
__global__ __launch_bounds__(256, 3)
void bilateral_kernel(const float* __restrict__ in, float* __restrict__ out)
{
    __shared__ float smf[14 * RSTR];   // 47712 B
    const int tx = threadIdx.x, ty = threadIdx.y;
    const int X0 = blockIdx.x * 64;
    const int Y0 = blockIdx.y * 8;
    const int b  = blockIdx.z;
    const float* __restrict__ inb = in + (size_t)b * 18 * HWs;

    // ---- fill channel-interleaved SMEM (+halo), sentinel for OOB ----
    const int tid = ty * 64 + tx;
    for (int i = tid; i < 14 * XW; i += 256) {
        int r = i / XW;
        int x = i - r * XW;
        int gy = Y0 - 3 + r;
        int gx = X0 - 3 + x;
        bool ok = ((unsigned)gx < WW) & ((unsigned)gy < HH);
        const float* g = inb + (size_t)gy * WW + gx;
        float4 u0, u1;
        u0.x = ok ? g[0 * HWs] : BIGV;
        u0.y = ok ? g[1 * HWs] : BIGV;
        u0.z = ok ? g[2 * HWs] : BIGV;
        u0.w = ok ? g[3 * HWs] : BIGV;
        u1.x = ok ? g[4 * HWs] : BIGV;
        u1.y = ok ? g[5 * HWs] : BIGV;
        u1.z = ok ? g[6 * HWs] : BIGV;
        u1.w = ok ? g[7 * HWs] : BIGV;
        float4* d = (float4*)&smf[r * RSTR + x * PSTR];
        d[0] = u0;
        d[1] = u1;
    }
    __syncthreads();

    const int gx = X0 + tx;
    const int ya = Y0 + 2 * ty;      // pixel a; pixel b = ya + 1

    // ---- per-pixel precompute: rp' = -(p^2)*log2(e), u = -2 rp' f, v = sum rp' f^2 ----
    ull rppA[4], rppB[4], upA[4], upB[4];
    float va = 0.f, vb = 0.f;
    const float* __restrict__ pa = inb + 8 * HWs + (size_t)ya * WW + gx;
    const float* __restrict__ pbp = pa + WW;
    const float* __restrict__ ca = &smf[(2 * ty + 3) * RSTR + (tx + 3) * PSTR];
    const float* __restrict__ cb = ca + RSTR;
    #pragma unroll
    for (int k = 0; k < 4; k++) {
        float p0a = pa[(2*k) * HWs],  p1a = pa[(2*k+1) * HWs];
        float p0b = pbp[(2*k) * HWs], p1b = pbp[(2*k+1) * HWs];
        float r0a = -(p0a * p0a) * L2E, r1a = -(p1a * p1a) * L2E;
        float r0b = -(p0b * p0b) * L2E, r1b = -(p1b * p1b) * L2E;
        float f0a = ca[2*k], f1a = ca[2*k+1];
        float f0b = cb[2*k], f1b = cb[2*k+1];
        va = fmaf(r0a * f0a, f0a, va); va = fmaf(r1a * f1a, f1a, va);
        vb = fmaf(r0b * f0b, f0b, vb); vb = fmaf(r1b * f1b, f1b, vb);
        rppA[k] = pk(r0a, r1a);
        rppB[k] = pk(r0b, r1b);
        upA[k]  = pk(-2.f * r0a * f0a, -2.f * r1a * f1a);
        upB[k]  = pk(-2.f * r0b * f0b, -2.f * r1b * f1b);
    }
    float qa, qb;
    qa = pa[8 * HWs];  qb = pbp[8 * HWs];
    const float sxa = -(qa * qa) * L2E, sxb = -(qb * qb) * L2E;
    qa = pa[9 * HWs];  qb = pbp[9 * HWs];
    const float sya = -(qa * qa) * L2E, syb = -(qb * qb) * L2E;

    ull acc01a = 0ULL, acc01b = 0ULL;
    float acc2a = 0.f, wsa = 0.f;
    float acc2b = 0.f, wsb = 0.f;

    // ---- main loop over 8 absolute rows, unrolled x2; dx & channels unrolled ----
    #pragma unroll 2
    for (int rr = 0; rr < 8; rr++) {
        int r = 2 * ty + rr;
        float da = (float)(rr - 3), db = (float)(rr - 4);
        float rba = (rr <= 6) ? fmaf(sya, da * da, va) : NEGB;  // mask invalid row, px a
        float rbb = (rr >= 1) ? fmaf(syb, db * db, vb) : NEGB;  // mask invalid row, px b
        const float* __restrict__ rowp = &smf[r * RSTR + tx * PSTR];
        #pragma unroll
        for (int dx = 0; dx < 7; dx++) {
            const float ddv = (float)((dx - 3) * (dx - 3));
            float ba = (dx == 3) ? rba : fmaf(sxa, ddv, rba);
            float bb = (dx == 3) ? rbb : fmaf(sxb, ddv, rbb);

            const ulonglong2* __restrict__ p = (const ulonglong2*)(rowp + dx * PSTR);
            ulonglong2 q0 = p[0];            // LDS.128: f01, f23
            ulonglong2 q1 = p[1];            // LDS.128: f45, f67
            ull f01 = q0.x, f23 = q0.y, f45 = q1.x, f67 = q1.y;

            // two 4-deep chains per pixel instead of one 8-deep
            ull lwa1 = pk(ba, 0.f), lwa2;
            ull lwb1 = pk(bb, 0.f), lwb2;
            {
                ull s;
                s = fma2(rppA[0], f01, upA[0]); lwa1 = fma2(s, f01, lwa1);
                s = fma2(rppB[0], f01, upB[0]); lwb1 = fma2(s, f01, lwb1);
                s = fma2(rppA[1], f23, upA[1]); lwa1 = fma2(s, f23, lwa1);
                s = fma2(rppB[1], f23, upB[1]); lwb1 = fma2(s, f23, lwb1);
                s = fma2(rppA[2], f45, upA[2]); lwa2 = fma2(s, f45, 0ULL);
                s = fma2(rppB[2], f45, upB[2]); lwb2 = fma2(s, f45, 0ULL);
                s = fma2(rppA[3], f67, upA[3]); lwa2 = fma2(s, f67, lwa2);
                s = fma2(rppB[3], f67, upB[3]); lwb2 = fma2(s, f67, lwb2);
            }
            ull lwa = add2(lwa1, lwa2);
            ull lwb = add2(lwb1, lwb2);
            float ea, oa, eb, ob2;
            upk(lwa, ea, oa);
            upk(lwb, eb, ob2);
            float wa = ex2(ea + oa);
            float wb = ex2(eb + ob2);

            // packed accumulate for channels 0,1; scalar for channel 2 + wsum
            acc01a = fma2(pk(wa, wa), f01, acc01a);
            acc01b = fma2(pk(wb, wb), f01, acc01b);
            float f2, f3u;
            upk(f23, f2, f3u);
            acc2a = fmaf(wa, f2, acc2a);  wsa += wa;
            acc2b = fmaf(wb, f2, acc2b);  wsb += wb;
        }
    }

    const float ia = frcp(wsa), ib = frcp(wsb);
    float a0, a1;
    float* __restrict__ oa = out + (size_t)b * 3 * HWs + (size_t)ya * WW + gx;
    float* __restrict__ ob = oa + WW;
    upk(acc01a, a0, a1);
    oa[0]   = a0 * ia;  oa[HWs] = a1 * ia;  oa[2 * HWs] = acc2a * ia;
    upk(acc01b, a0, a1);
    ob[0]   = a0 * ib;  ob[HWs] = a1 * ib;  ob[2 * HWs] = acc2b * ib;
}

extern "C" void kernel_launch(void* const* d_in, const int* in_sizes, int n_in,
                              void* d_out, int out_size) {
    const float* in = (const float*)d_in[0];
    float* out = (float*)d_out;
    dim3 grid(WW / 64, HH / 8, 2);
    dim3 block(64, 4);
    bilateral_kernel<<<grid, block>>>(in, out);
}

// round 9
// speedup vs baseline: 1.1371x; 1.1371x over previous
#include <cuda_runtime.h>
#include <cstdint>

#define HH 1024
#define WW 1024
#define HWs (HH*WW)
#define BIGV 1e9f
#define L2E 1.4426950408889634f

#define XW 71          // x window: [X0-3, X0+67]
#define PSTR 12        // floats per pixel slot (8 ch + 4 pad -> 48B, 16B aligned for LDS.128)
#define RSTR (XW*PSTR) // floats per row

typedef unsigned long long ull;

__device__ __forceinline__ ull pk(float a, float b) {
    ull r;
    asm("mov.b64 %0, {%1, %2};" : "=l"(r) : "f"(a), "f"(b));
    return r;
}
__device__ __forceinline__ void upk(ull v, float& a, float& b) {
    asm("mov.b64 {%0, %1}, %2;" : "=f"(a), "=f"(b) : "l"(v));
}
__device__ __forceinline__ ull fma2(ull a, ull b, ull c) {
    ull d;
    asm("fma.rn.f32x2 %0, %1, %2, %3;" : "=l"(d) : "l"(a), "l"(b), "l"(c));
    return d;
}
__device__ __forceinline__ float ex2(float x) {
    float y;
    asm("ex2.approx.f32 %0, %1;" : "=f"(y) : "f"(x));
    return y;
}
__device__ __forceinline__ float frcp(float x) {
    float y;
    asm("rcp.approx.f32 %0, %1;" : "=f"(y) : "f"(x));
    return y;
}

// Tile 64 wide x 8 tall. Block (64,4); thread (tx,ty) owns pixels
// (X0+tx, Y0+2ty) and (X0+tx, Y0+2ty+1) — vertically adjacent; each loaded
// neighbor value serves BOTH pixels. SMEM channel-interleaved, 48B pixel slot,
// channels fetched by TWO LDS.128 (conflict-free at stride-12 words).
// R9: rows rr=0 / rr=7 peeled into single-pixel bodies (no masked-out chain
// work); {acc2, wsum} packed with register-built {f2, 1.0} operand.
__global__ __launch_bounds__(256, 3)
void bilateral_kernel(const float* __restrict__ in, float* __restrict__ out)
{
    __shared__ float smf[14 * RSTR];   // 47712 B
    const int tx = threadIdx.x, ty = threadIdx.y;
    const int X0 = blockIdx.x * 64;
    const int Y0 = blockIdx.y * 8;
    const int b  = blockIdx.z;
    const float* __restrict__ inb = in + (size_t)b * 18 * HWs;

    // ---- fill channel-interleaved SMEM (+halo), sentinel for OOB ----
    const int tid = ty * 64 + tx;
    for (int i = tid; i < 14 * XW; i += 256) {
        int r = i / XW;
        int x = i - r * XW;
        int gy = Y0 - 3 + r;
        int gx = X0 - 3 + x;
        bool ok = ((unsigned)gx < WW) & ((unsigned)gy < HH);
        const float* g = inb + (size_t)gy * WW + gx;
        float4 u0, u1;
        u0.x = ok ? g[0 * HWs] : BIGV;
        u0.y = ok ? g[1 * HWs] : BIGV;
        u0.z = ok ? g[2 * HWs] : BIGV;
        u0.w = ok ? g[3 * HWs] : BIGV;
        u1.x = ok ? g[4 * HWs] : BIGV;
        u1.y = ok ? g[5 * HWs] : BIGV;
        u1.z = ok ? g[6 * HWs] : BIGV;
        u1.w = ok ? g[7 * HWs] : BIGV;
        float4* d = (float4*)&smf[r * RSTR + x * PSTR];
        d[0] = u0;
        d[1] = u1;
    }
    __syncthreads();

    const int gx = X0 + tx;
    const int ya = Y0 + 2 * ty;      // pixel a; pixel b = ya + 1

    // ---- per-pixel precompute: rp' = -(p^2)*log2(e), u = -2 rp' f, v = sum rp' f^2 ----
    ull rppA[4], rppB[4], upA[4], upB[4];
    float va = 0.f, vb = 0.f;
    const float* __restrict__ pa = inb + 8 * HWs + (size_t)ya * WW + gx;
    const float* __restrict__ pbp = pa + WW;
    const float* __restrict__ ca = &smf[(2 * ty + 3) * RSTR + (tx + 3) * PSTR];
    const float* __restrict__ cb = ca + RSTR;
    #pragma unroll
    for (int k = 0; k < 4; k++) {
        float p0a = pa[(2*k) * HWs],  p1a = pa[(2*k+1) * HWs];
        float p0b = pbp[(2*k) * HWs], p1b = pbp[(2*k+1) * HWs];
        float r0a = -(p0a * p0a) * L2E, r1a = -(p1a * p1a) * L2E;
        float r0b = -(p0b * p0b) * L2E, r1b = -(p1b * p1b) * L2E;
        float f0a = ca[2*k], f1a = ca[2*k+1];
        float f0b = cb[2*k], f1b = cb[2*k+1];
        va = fmaf(r0a * f0a, f0a, va); va = fmaf(r1a * f1a, f1a, va);
        vb = fmaf(r0b * f0b, f0b, vb); vb = fmaf(r1b * f1b, f1b, vb);
        rppA[k] = pk(r0a, r1a);
        rppB[k] = pk(r0b, r1b);
        upA[k]  = pk(-2.f * r0a * f0a, -2.f * r1a * f1a);
        upB[k]  = pk(-2.f * r0b * f0b, -2.f * r1b * f1b);
    }
    float qa, qb;
    qa = pa[8 * HWs];  qb = pbp[8 * HWs];
    const float sxa = -(qa * qa) * L2E, sxb = -(qb * qb) * L2E;
    qa = pa[9 * HWs];  qb = pbp[9 * HWs];
    const float sya = -(qa * qa) * L2E, syb = -(qb * qb) * L2E;

    ull acc01a = 0ULL, acc01b = 0ULL;
    ull acc2wsa = 0ULL, acc2wsb = 0ULL;   // packed {acc2, wsum}
    const float onef = 1.0f;

    // chain macro: 8-deep packed logw chain for one pixel
    #define CHAIN(RPP, UP, LW)                                   \
        { ull s_;                                                \
          s_ = fma2(RPP[0], f01, UP[0]); LW = fma2(s_, f01, LW); \
          s_ = fma2(RPP[1], f23, UP[1]); LW = fma2(s_, f23, LW); \
          s_ = fma2(RPP[2], f45, UP[2]); LW = fma2(s_, f45, LW); \
          s_ = fma2(RPP[3], f67, UP[3]); LW = fma2(s_, f67, LW); }

    // ---- peeled row rr=0: pixel a only (dy = -3) ----
    {
        const float rba = fmaf(sya, 9.f, va);
        const float* __restrict__ rowp = &smf[(2 * ty) * RSTR + tx * PSTR];
        #pragma unroll
        for (int dx = 0; dx < 7; dx++) {
            const float ddv = (float)((dx - 3) * (dx - 3));
            float ba = (dx == 3) ? rba : fmaf(sxa, ddv, rba);
            const ulonglong2* __restrict__ p = (const ulonglong2*)(rowp + dx * PSTR);
            ulonglong2 q0 = p[0], q1 = p[1];
            ull f01 = q0.x, f23 = q0.y, f45 = q1.x, f67 = q1.y;
            ull lwa = pk(ba, 0.f);
            CHAIN(rppA, upA, lwa);
            float ea, oa;
            upk(lwa, ea, oa);
            float wa = ex2(ea + oa);
            ull wwa = pk(wa, wa);
            float f2, f3u;
            upk(f23, f2, f3u);
            ull pf21 = pk(f2, onef);
            acc01a  = fma2(wwa, f01,  acc01a);
            acc2wsa = fma2(wwa, pf21, acc2wsa);
        }
    }

    // ---- main rows rr=1..6: both pixels, no masking ----
    for (int rr = 1; rr < 7; rr++) {
        int r = 2 * ty + rr;
        float da = (float)(rr - 3), db = (float)(rr - 4);
        float rba = fmaf(sya, da * da, va);
        float rbb = fmaf(syb, db * db, vb);
        const float* __restrict__ rowp = &smf[r * RSTR + tx * PSTR];
        #pragma unroll
        for (int dx = 0; dx < 7; dx++) {
            const float ddv = (float)((dx - 3) * (dx - 3));
            float ba = (dx == 3) ? rba : fmaf(sxa, ddv, rba);
            float bb = (dx == 3) ? rbb : fmaf(sxb, ddv, rbb);
            const ulonglong2* __restrict__ p = (const ulonglong2*)(rowp + dx * PSTR);
            ulonglong2 q0 = p[0], q1 = p[1];
            ull f01 = q0.x, f23 = q0.y, f45 = q1.x, f67 = q1.y;

            ull lwa = pk(ba, 0.f);
            ull lwb = pk(bb, 0.f);
            {
                ull s;
                s = fma2(rppA[0], f01, upA[0]); lwa = fma2(s, f01, lwa);
                s = fma2(rppB[0], f01, upB[0]); lwb = fma2(s, f01, lwb);
                s = fma2(rppA[1], f23, upA[1]); lwa = fma2(s, f23, lwa);
                s = fma2(rppB[1], f23, upB[1]); lwb = fma2(s, f23, lwb);
                s = fma2(rppA[2], f45, upA[2]); lwa = fma2(s, f45, lwa);
                s = fma2(rppB[2], f45, upB[2]); lwb = fma2(s, f45, lwb);
                s = fma2(rppA[3], f67, upA[3]); lwa = fma2(s, f67, lwa);
                s = fma2(rppB[3], f67, upB[3]); lwb = fma2(s, f67, lwb);
            }
            float ea, oa, eb, ob2;
            upk(lwa, ea, oa);
            upk(lwb, eb, ob2);
            float wa = ex2(ea + oa);
            float wb = ex2(eb + ob2);
            ull wwa = pk(wa, wa);
            ull wwb = pk(wb, wb);
            float f2, f3u;
            upk(f23, f2, f3u);
            ull pf21 = pk(f2, onef);
            acc01a  = fma2(wwa, f01,  acc01a);
            acc2wsa = fma2(wwa, pf21, acc2wsa);
            acc01b  = fma2(wwb, f01,  acc01b);
            acc2wsb = fma2(wwb, pf21, acc2wsb);
        }
    }

    // ---- peeled row rr=7: pixel b only (dy = +3) ----
    {
        const float rbb = fmaf(syb, 9.f, vb);
        const float* __restrict__ rowp = &smf[(2 * ty + 7) * RSTR + tx * PSTR];
        #pragma unroll
        for (int dx = 0; dx < 7; dx++) {
            const float ddv = (float)((dx - 3) * (dx - 3));
            float bb = (dx == 3) ? rbb : fmaf(sxb, ddv, rbb);
            const ulonglong2* __restrict__ p = (const ulonglong2*)(rowp + dx * PSTR);
            ulonglong2 q0 = p[0], q1 = p[1];
            ull f01 = q0.x, f23 = q0.y, f45 = q1.x, f67 = q1.y;
            ull lwb = pk(bb, 0.f);
            CHAIN(rppB, upB, lwb);
            float eb, ob2;
            upk(lwb, eb, ob2);
            float wb = ex2(eb + ob2);
            ull wwb = pk(wb, wb);
            float f2, f3u;
            upk(f23, f2, f3u);
            ull pf21 = pk(f2, onef);
            acc01b  = fma2(wwb, f01,  acc01b);
            acc2wsb = fma2(wwb, pf21, acc2wsb);
        }
    }
    #undef CHAIN

    float acc2a, wsa, acc2b, wsb, a0, a1;
    upk(acc2wsa, acc2a, wsa);
    upk(acc2wsb, acc2b, wsb);
    const float ia = frcp(wsa), ib = frcp(wsb);
    float* __restrict__ oa = out + (size_t)b * 3 * HWs + (size_t)ya * WW + gx;
    float* __restrict__ ob = oa + WW;
    upk(acc01a, a0, a1);
    oa[0]   = a0 * ia;  oa[HWs] = a1 * ia;  oa[2 * HWs] = acc2a * ia;
    upk(acc01b, a0, a1);
    ob[0]   = a0 * ib;  ob[HWs] = a1 * ib;  ob[2 * HWs] = acc2b * ib;
}

extern "C" void kernel_launch(void* const* d_in, const int* in_sizes, int n_in,
                              void* d_out, int out_size) {
    const float* in = (const float*)d_in[0];
    float* out = (float*)d_out;
    dim3 grid(WW / 64, HH / 8, 2);
    dim3 block(64, 4);
    bilateral_kernel<<<grid, block>>>(in, out);
}